// round 3
// baseline (speedup 1.0000x reference)
#include <cuda_runtime.h>

// Problem constants
#define BB 4
#define NN 4096
#define DD 1024
#define L  32                 // timesteps per chunk
#define C  (NN / L)           // 128 chunks per chain
#define DT 256                // threads per block = d-tile width
#define NCOL (BB * (DD / DT)) // 16 independent chains
#define NBLK (C * NCOL)       // 2048 blocks

// Scratch (static __device__ globals: allowed; no runtime allocation)
__device__ float2 g_agg [NBLK * DT];
__device__ float2 g_incl[NBLK * DT];
__device__ int    g_flags[NBLK];     // 0 = empty, 1 = aggregate ready, 2 = inclusive ready

__device__ __forceinline__ int ld_acquire(const int* p) {
    int v;
    asm volatile("ld.global.acquire.gpu.b32 %0, [%1];" : "=r"(v) : "l"(p) : "memory");
    return v;
}
__device__ __forceinline__ void st_release(int* p, int v) {
    asm volatile("st.global.release.gpu.b32 [%0], %1;" :: "l"(p), "r"(v) : "memory");
}

__global__ __launch_bounds__(DT)
void assoc_scan_kernel(const float* __restrict__ gates,
                       const float* __restrict__ inputs,
                       float* __restrict__ out)
{
    const int bx    = blockIdx.x;
    const int chunk = bx >> 4;        // slow-varying -> predecessors always scheduled first
    const int col   = bx & 15;        // chain id: (b, d-tile)
    const int b     = col >> 2;
    const int dt    = col & 3;
    const int tid   = threadIdx.x;
    const int d     = dt * DT + tid;

    const long base = ((long)b * NN + (long)chunk * L) * (long)DD + d;

    // ---- Load chunk into registers (fully unrolled -> high MLP, coalesced) ----
    float gv[L], xv[L];
#pragma unroll
    for (int t = 0; t < L; t++) {
        gv[t] = __ldg(gates  + base + (long)t * DD);
        xv[t] = __ldg(inputs + base + (long)t * DD);
    }

    // ---- Local chunk aggregate: (A = prod g, S = scan value with h_in = 0) ----
    float A = 1.0f, S = 0.0f;
#pragma unroll
    for (int t = 0; t < L; t++) {
        S = fmaf(gv[t], S, xv[t]);
        A = A * gv[t];
    }

    const int slot = bx * DT + tid;
    float accA = 1.0f, accS = 0.0f;   // exclusive prefix (carry) for this chunk

    if (chunk == 0) {
        float2 v; v.x = A; v.y = S;
        __stcg(&g_incl[slot], v);
        __threadfence();
        __syncthreads();
        if (tid == 0) st_release(&g_flags[bx], 2);
    } else {
        // Publish aggregate ASAP so successors can make progress.
        float2 v; v.x = A; v.y = S;
        __stcg(&g_agg[slot], v);
        __threadfence();
        __syncthreads();
        if (tid == 0) st_release(&g_flags[bx], 1);

        // ---- Windowed decoupled lookback: up to 32 predecessors per round ----
        __shared__ int s_take;
        __shared__ int s_done;
        int k_hi = chunk - 1;
        for (;;) {
            const int W = (k_hi + 1 < 32) ? (k_hi + 1) : 32;
            if (tid < 32) {
                int take = 0, done = 0;
                const unsigned valid = (W == 32) ? 0xffffffffu : ((1u << W) - 1u);
                for (;;) {
                    int f = 2;
                    if (tid < W) f = ld_acquire(&g_flags[(k_hi - tid) * 16 + col]);
                    unsigned m1 = __ballot_sync(0xffffffffu, f >= 1) & valid;
                    unsigned m2 = __ballot_sync(0xffffffffu, f == 2) & valid;
                    if (m2) {
                        const int s = __ffs(m2) - 1;           // newest inclusive in window
                        const unsigned need = (s == 0) ? 0u : ((1u << s) - 1u);
                        if ((m1 & need) == need) { take = s + 1; done = 1; break; }
                    }
                    if (m1 == valid) { take = W; done = 0; break; }
                }
                if (tid == 0) { s_take = take; s_done = done; }
            }
            __syncthreads();
            const int take = s_take;
            const int done = s_done;

            // Fold 'take' predecessors, newest (j=0) to oldest, in MLP-8 batches.
            for (int j0 = 0; j0 < take; j0 += 8) {
                float2 p[8];
                const int nb = (take - j0 < 8) ? (take - j0) : 8;
#pragma unroll
                for (int j = 0; j < 8; j++) {
                    if (j < nb) {
                        const int k = k_hi - (j0 + j);
                        const float2* src = (done && (j0 + j == take - 1)) ? g_incl : g_agg;
                        p[j] = __ldcg(&src[(k * 16 + col) * DT + tid]);
                    }
                }
#pragma unroll
                for (int j = 0; j < 8; j++) {
                    if (j < nb) {
                        accS = fmaf(accA, p[j].y, accS);  // fold older segment under acc
                        accA = accA * p[j].x;
                    }
                }
            }
            __syncthreads();   // protect s_take/s_done reuse
            if (done) break;
            k_hi -= take;      // done==0 implies window never reached an inclusive; k_hi >= 0
        }

        // Publish our inclusive prefix: combine(all-predecessors, local)
        float2 inc;
        inc.x = A * accA;
        inc.y = fmaf(A, accS, S);
        __stcg(&g_incl[slot], inc);
        __threadfence();
        __syncthreads();
        if (tid == 0) st_release(&g_flags[bx], 2);
    }

    // ---- Emit outputs from registers with the carry-in ----
    float h = accS;
#pragma unroll
    for (int t = 0; t < L; t++) {
        h = fmaf(gv[t], h, xv[t]);
        out[base + (long)t * DD] = h;
    }
}

extern "C" void kernel_launch(void* const* d_in, const int* in_sizes, int n_in,
                              void* d_out, int out_size)
{
    const float* gates  = (const float*)d_in[0];
    const float* inputs = (const float*)d_in[1];
    float*       out    = (float*)d_out;

    void* flags_ptr = nullptr;
    cudaGetSymbolAddress(&flags_ptr, g_flags);
    cudaMemsetAsync(flags_ptr, 0, NBLK * sizeof(int));   // reset chain state (captured node)

    assoc_scan_kernel<<<NBLK, DT>>>(gates, inputs, out);
}

// round 4
// speedup vs baseline: 1.0871x; 1.0871x over previous
#include <cuda_runtime.h>

// Problem constants
#define BB 4
#define NN 4096
#define DD 1024
#define L  32                 // timesteps per chunk
#define C  (NN / L)           // 128 chunks per chain
#define DT 256                // threads per block = d-tile width
#define NCOL (BB * (DD / DT)) // 16 independent chains
#define NBLK (C * NCOL)       // 2048 blocks
#define W  8                  // lookback window width

// Scratch (static __device__ globals: allowed; no runtime allocation)
__device__ float2 g_agg [NBLK * DT];
__device__ float2 g_incl[NBLK * DT];
__device__ int    g_flags[NBLK];     // 0 = empty, 1 = aggregate ready, 2 = inclusive ready

__device__ __forceinline__ int ld_acquire(const int* p) {
    int v;
    asm volatile("ld.global.acquire.gpu.b32 %0, [%1];" : "=r"(v) : "l"(p) : "memory");
    return v;
}
__device__ __forceinline__ void st_release(int* p, int v) {
    asm volatile("st.global.release.gpu.b32 [%0], %1;" :: "l"(p), "r"(v) : "memory");
}

__global__ __launch_bounds__(DT, 3)
void assoc_scan_kernel(const float* __restrict__ gates,
                       const float* __restrict__ inputs,
                       float* __restrict__ out)
{
    const int bx    = blockIdx.x;
    const int chunk = bx >> 4;        // slow-varying -> predecessors scheduled first
    const int col   = bx & 15;        // chain id: (b, d-tile)
    const int tid   = threadIdx.x;

    // 32-bit element offset: max = 4*4096*1024 = 2^24, fits easily.
    const int base = ((col >> 2) * NN + chunk * L) * DD + ((col & 3) * DT + tid);

    // ---- Load chunk into registers (fully unrolled, coalesced, evict-first) ----
    float gv[L], xv[L];
#pragma unroll
    for (int t = 0; t < L; t++) {
        gv[t] = __ldcs(gates  + base + t * DD);
        xv[t] = __ldcs(inputs + base + t * DD);
    }

    // ---- Local chunk aggregate: (A = prod g, S = scan with h_in = 0) ----
    float A = 1.0f, S = 0.0f;
#pragma unroll
    for (int t = 0; t < L; t++) {
        S = fmaf(gv[t], S, xv[t]);
        A = A * gv[t];
    }

    const int slot = bx * DT + tid;
    float accA = 1.0f, accS = 0.0f;   // exclusive prefix (carry) for this chunk

    if (chunk == 0) {
        float2 v; v.x = A; v.y = S;
        __stcg(&g_incl[slot], v);
        __threadfence();
        __syncthreads();
        if (tid == 0) st_release(&g_flags[bx], 2);
    } else {
        // Publish aggregate ASAP so successors can make progress.
        float2 v; v.x = A; v.y = S;
        __stcg(&g_agg[slot], v);
        __threadfence();
        __syncthreads();
        if (tid == 0) st_release(&g_flags[bx], 1);

        // ---- Windowed decoupled lookback: up to W predecessors per round ----
        __shared__ int s_take, s_done;
        int k_hi = chunk - 1;
        for (;;) {
            const int Wc = (k_hi + 1 < W) ? (k_hi + 1) : W;
            if (tid < 32) {
                int take, done;
                const unsigned valid = (1u << Wc) - 1u;
                for (;;) {
                    int f = 2;
                    if (tid < Wc) f = ld_acquire(&g_flags[(k_hi - tid) * 16 + col]);
                    unsigned m1 = __ballot_sync(0xffffffffu, f >= 1) & valid;
                    unsigned m2 = __ballot_sync(0xffffffffu, f == 2) & valid;
                    if (m2) {
                        const int s = __ffs(m2) - 1;           // newest inclusive in window
                        const unsigned need = (1u << s) - 1u;  // all newer must have aggregates
                        if ((m1 & need) == need) { take = s + 1; done = 1; break; }
                    }
                    if (m1 == valid) { take = Wc; done = 0; break; }
                    __nanosleep(60);                            // backoff: don't hammer L2
                }
                if (tid == 0) { s_take = take; s_done = done; }
            }
            __syncthreads();
            const int take = s_take;
            const int done = s_done;

            // Fold 'take' predecessors, newest (j=0) to oldest, batches of 4 (MLP 4).
            for (int j0 = 0; j0 < take; j0 += 4) {
                const int nb = (take - j0 < 4) ? (take - j0) : 4;
                float2 p0, p1, p2, p3;
                {
                    const int j = j0;
                    const float2* s0 = (done && (j   == take - 1)) ? g_incl : g_agg;
                    p0 = __ldcg(&s0[((k_hi - j) * 16 + col) * DT + tid]);
                }
                if (nb > 1) { const int j = j0+1; const float2* s1 = (done && (j == take-1)) ? g_incl : g_agg;
                              p1 = __ldcg(&s1[((k_hi - j) * 16 + col) * DT + tid]); }
                if (nb > 2) { const int j = j0+2; const float2* s2 = (done && (j == take-1)) ? g_incl : g_agg;
                              p2 = __ldcg(&s2[((k_hi - j) * 16 + col) * DT + tid]); }
                if (nb > 3) { const int j = j0+3; const float2* s3 = (done && (j == take-1)) ? g_incl : g_agg;
                              p3 = __ldcg(&s3[((k_hi - j) * 16 + col) * DT + tid]); }

                accS = fmaf(accA, p0.y, accS); accA *= p0.x;
                if (nb > 1) { accS = fmaf(accA, p1.y, accS); accA *= p1.x; }
                if (nb > 2) { accS = fmaf(accA, p2.y, accS); accA *= p2.x; }
                if (nb > 3) { accS = fmaf(accA, p3.y, accS); accA *= p3.x; }
            }
            __syncthreads();   // protect s_take/s_done reuse
            if (done) break;
            k_hi -= take;      // window exhausted without inclusive; chunk0 is always 2 -> no deadlock
        }

        // Publish our inclusive prefix: combine(all-predecessors, local)
        float2 inc;
        inc.x = A * accA;
        inc.y = fmaf(A, accS, S);
        __stcg(&g_incl[slot], inc);
        __threadfence();
        __syncthreads();
        if (tid == 0) st_release(&g_flags[bx], 2);
    }

    // ---- Emit outputs from registers with the carry-in (evict-first stores) ----
    float h = accS;
#pragma unroll
    for (int t = 0; t < L; t++) {
        h = fmaf(gv[t], h, xv[t]);
        __stcs(out + base + t * DD, h);
    }
}

extern "C" void kernel_launch(void* const* d_in, const int* in_sizes, int n_in,
                              void* d_out, int out_size)
{
    const float* gates  = (const float*)d_in[0];
    const float* inputs = (const float*)d_in[1];
    float*       out    = (float*)d_out;

    void* flags_ptr = nullptr;
    cudaGetSymbolAddress(&flags_ptr, g_flags);
    cudaMemsetAsync(flags_ptr, 0, NBLK * sizeof(int));   // reset chain state (captured node)

    assoc_scan_kernel<<<NBLK, DT>>>(gates, inputs, out);
}

// round 5
// speedup vs baseline: 1.7706x; 1.6288x over previous
#include <cuda_runtime.h>

// Problem constants
#define BB 4
#define NN 4096
#define DD 1024
#define L  32                 // timesteps per chunk
#define C  (NN / L)           // 128 chunks per chain
#define DT 256                // threads per block = d-tile width
#define NCOL (BB * (DD / DT)) // 16 independent chains
#define NBLK (C * NCOL)       // 2048 blocks
#define W  16                 // lookback window width

// Scratch (static __device__ globals: allowed; no runtime allocation)
__device__ float2 g_agg [NBLK * DT];
__device__ float2 g_incl[NBLK * DT];
__device__ int    g_flags[NBLK];     // 0 = empty, 1 = aggregate ready, 2 = inclusive ready

// Plain L2 poll: no acquire semantics, no atomic ALU serialization, not hoistable.
__device__ __forceinline__ int ld_flag_cg(const int* p) {
    int v;
    asm volatile("ld.global.cg.b32 %0, [%1];" : "=r"(v) : "l"(p) : "memory");
    return v;
}

__global__ __launch_bounds__(DT, 3)
void assoc_scan_kernel(const float* __restrict__ gates,
                       const float* __restrict__ inputs,
                       float* __restrict__ out)
{
    const int bx    = blockIdx.x;
    const int chunk = bx >> 4;        // slow-varying -> predecessors scheduled first
    const int col   = bx & 15;        // chain id: (b, d-tile)
    const int tid   = threadIdx.x;

    const int base = ((col >> 2) * NN + chunk * L) * DD + ((col & 3) * DT + tid);

    // ---- Load chunk into registers (fully unrolled, coalesced, high MLP) ----
    float gv[L], xv[L];
#pragma unroll
    for (int t = 0; t < L; t++) {
        gv[t] = __ldg(gates  + base + t * DD);
        xv[t] = __ldg(inputs + base + t * DD);
    }

    // ---- Local chunk aggregate: (A = prod g, S = scan with h_in = 0) ----
    float A = 1.0f, S = 0.0f;
#pragma unroll
    for (int t = 0; t < L; t++) {
        S = fmaf(gv[t], S, xv[t]);
        A = A * gv[t];
    }

    const int slot = bx * DT + tid;
    float accA = 1.0f, accS = 0.0f;   // exclusive prefix (carry) for this chunk

    if (chunk == 0) {
        float2 v; v.x = A; v.y = S;
        __stcg(&g_incl[slot], v);
        __threadfence();
        __syncthreads();
        if (tid == 0) atomicExch(&g_flags[bx], 2);
    } else {
        // Publish aggregate ASAP so successors can make progress.
        float2 v; v.x = A; v.y = S;
        __stcg(&g_agg[slot], v);
        __threadfence();
        __syncthreads();
        if (tid == 0) atomicExch(&g_flags[bx], 1);

        // ---- Windowed decoupled lookback (R2 primitives, W=16 ballot window) ----
        __shared__ int s_take, s_done;
        int k_hi = chunk - 1;
        for (;;) {
            const int Wc = (k_hi + 1 < W) ? (k_hi + 1) : W;
            if (tid < 32) {
                int take, done;
                const unsigned valid = (1u << Wc) - 1u;   // Wc <= 16, no shift overflow
                for (;;) {
                    int f = 2;
                    if (tid < Wc) f = ld_flag_cg(&g_flags[(k_hi - tid) * 16 + col]);
                    unsigned m1 = __ballot_sync(0xffffffffu, f >= 1) & valid;
                    unsigned m2 = __ballot_sync(0xffffffffu, f == 2) & valid;
                    if (m2) {
                        const int s = __ffs(m2) - 1;           // newest inclusive in window
                        const unsigned need = (1u << s) - 1u;  // newer entries need aggregates
                        if ((m1 & need) == need) { take = s + 1; done = 1; break; }
                    }
                    if (m1 == valid) { take = Wc; done = 0; break; }
                }
                if (tid == 0) { s_take = take; s_done = done; }
            }
            __syncthreads();
            const int take = s_take;
            const int done = s_done;

            // Fold 'take' predecessors, newest (j=0) to oldest, MLP-4 batches.
            for (int j0 = 0; j0 < take; j0 += 4) {
                const int nb = (take - j0 < 4) ? (take - j0) : 4;
                float2 p0, p1, p2, p3;
                {            const int j = j0;     const float2* s = (done && (j == take-1)) ? g_incl : g_agg;
                             p0 = __ldcg(&s[((k_hi - j) * 16 + col) * DT + tid]); }
                if (nb > 1) { const int j = j0 + 1; const float2* s = (done && (j == take-1)) ? g_incl : g_agg;
                             p1 = __ldcg(&s[((k_hi - j) * 16 + col) * DT + tid]); }
                if (nb > 2) { const int j = j0 + 2; const float2* s = (done && (j == take-1)) ? g_incl : g_agg;
                             p2 = __ldcg(&s[((k_hi - j) * 16 + col) * DT + tid]); }
                if (nb > 3) { const int j = j0 + 3; const float2* s = (done && (j == take-1)) ? g_incl : g_agg;
                             p3 = __ldcg(&s[((k_hi - j) * 16 + col) * DT + tid]); }

                accS = fmaf(accA, p0.y, accS); accA *= p0.x;
                if (nb > 1) { accS = fmaf(accA, p1.y, accS); accA *= p1.x; }
                if (nb > 2) { accS = fmaf(accA, p2.y, accS); accA *= p2.x; }
                if (nb > 3) { accS = fmaf(accA, p3.y, accS); accA *= p3.x; }
            }
            __syncthreads();   // protect s_take/s_done reuse
            if (done) break;
            k_hi -= take;      // chunk 0 always posts inclusive -> guaranteed termination
        }

        // Publish our inclusive prefix: combine(all-predecessors, local)
        float2 inc;
        inc.x = A * accA;
        inc.y = fmaf(A, accS, S);
        __stcg(&g_incl[slot], inc);
        __threadfence();
        __syncthreads();
        if (tid == 0) atomicExch(&g_flags[bx], 2);
    }

    // ---- Emit outputs from registers with the carry-in ----
    float h = accS;
#pragma unroll
    for (int t = 0; t < L; t++) {
        h = fmaf(gv[t], h, xv[t]);
        out[base + t * DD] = h;
    }
}

extern "C" void kernel_launch(void* const* d_in, const int* in_sizes, int n_in,
                              void* d_out, int out_size)
{
    const float* gates  = (const float*)d_in[0];
    const float* inputs = (const float*)d_in[1];
    float*       out    = (float*)d_out;

    void* flags_ptr = nullptr;
    cudaGetSymbolAddress(&flags_ptr, g_flags);
    cudaMemsetAsync(flags_ptr, 0, NBLK * sizeof(int));   // reset chain state (captured node)

    assoc_scan_kernel<<<NBLK, DT>>>(gates, inputs, out);
}